// round 2
// baseline (speedup 1.0000x reference)
#include <cuda_runtime.h>
#include <cstdint>
#include <cstddef>

#define B_ 2
#define S_ 2048
#define D_ 64
#define H_ 8

#define TM 64    // rows per CTA
#define TN 64    // t-columns per main-loop iteration
#define NTHREADS 128

// pitch in 32-bit words; 72 ≡ 8 (mod 32) gives conflict-free LDS.64 fragment
// loads and conflict-free STS.128 staging for the pair-permuted layout.
#define PITCH 72

#define SMEM_WORDS (4 * TM * PITCH)         // sQ, sK, sV, sP (TM==TN)
#define SMEM_BYTES (SMEM_WORDS * 4)

__device__ __forceinline__ uint32_t f2tf(float x) {
    uint32_t r;
    asm("cvt.rna.tf32.f32 %0, %1;" : "=r"(r) : "f"(x));
    return r;
}

__device__ __forceinline__ void mma_tf32(float c[4],
                                         uint32_t a0, uint32_t a1, uint32_t a2, uint32_t a3,
                                         uint32_t b0, uint32_t b1) {
    asm volatile(
        "mma.sync.aligned.m16n8k8.row.col.f32.tf32.tf32.f32 "
        "{%0,%1,%2,%3}, {%4,%5,%6,%7}, {%8,%9}, {%0,%1,%2,%3};\n"
        : "+f"(c[0]), "+f"(c[1]), "+f"(c[2]), "+f"(c[3])
        : "r"(a0), "r"(a1), "r"(a2), "r"(a3), "r"(b0), "r"(b1));
}

// Stage one float4 (logical cols 4*c4 .. 4*c4+3 of an 8-col block) into the
// pair-permuted layout: within each 8-col block, logical col w goes to
// physical word perm(w) = (w&3)*2 + (w>>2), so fragment pairs (w, w+4)
// become adjacent words -> LDS.64 operand loads.
// Thread pair (lane ^ 1) covers one 8-col block; exchange via shuffles and
// each thread emits one STS.128.
__device__ __forceinline__ void store_permuted(uint32_t* base, int row, int c4,
                                               float4 v, float scale) {
    float s0 = __shfl_xor_sync(0xffffffffu, v.x, 1);
    float s1 = __shfl_xor_sync(0xffffffffu, v.y, 1);
    float s2 = __shfl_xor_sync(0xffffffffu, v.z, 1);
    float s3 = __shfl_xor_sync(0xffffffffu, v.w, 1);
    int blk  = c4 >> 1;
    int half = c4 & 1;
    uint4 o;
    if (half == 0) {
        o.x = f2tf(v.x * scale); o.y = f2tf(s0 * scale);
        o.z = f2tf(v.y * scale); o.w = f2tf(s1 * scale);
    } else {
        o.x = f2tf(s2 * scale);  o.y = f2tf(v.z * scale);
        o.z = f2tf(s3 * scale);  o.w = f2tf(v.w * scale);
    }
    *reinterpret_cast<uint4*>(base + row * PITCH + blk * 8 + half * 4) = o;
}

__global__ void __launch_bounds__(NTHREADS, 3)
attn_bias_kernel(const float* __restrict__ x1,
                 const float* __restrict__ x2,
                 const float* __restrict__ x3,
                 const float* __restrict__ x4,
                 float* __restrict__ out) {
    const int mt = blockIdx.x;   // 0..31  (row tile)
    const int h  = blockIdx.y;   // 0..7
    const int b  = blockIdx.z;   // 0..1

    const int tid  = threadIdx.x;
    const int warp = tid >> 5;
    const int lane = tid & 31;
    const int r = lane >> 2;     // 0..7
    const int q = lane & 3;      // 0..3

    extern __shared__ uint32_t smem[];
    uint32_t* sQ = smem;                 // [TM][PITCH] permuted tf32 (pre-scaled)
    uint32_t* sK = sQ + TM * PITCH;      // [TN][PITCH] permuted tf32
    uint32_t* sV = sK + TN * PITCH;      // [TN][PITCH] plain    tf32
    uint32_t* sP = sV + TN * PITCH;      // [TM][PITCH] permuted tf32

    // ---- stage Q tile once (scaled by 1/sqrt(D) = 0.125, exact in fp) ----
    const float* qbase = x1 + ((size_t)b * S_ + (size_t)mt * TM) * D_;
    #pragma unroll
    for (int i = tid; i < TM * (D_ / 4); i += NTHREADS) {
        int row = i >> 4;
        int c4  = i & 15;
        float4 v = *reinterpret_cast<const float4*>(qbase + row * D_ + c4 * 4);
        store_permuted(sQ, row, c4, v, 0.125f);
    }

    float accO[8][4];
    #pragma unroll
    for (int n = 0; n < 8; ++n)
        #pragma unroll
        for (int j = 0; j < 4; ++j) accO[n][j] = 0.0f;
    float lsum0 = 0.0f, lsum1 = 0.0f;

    const float* kbase = x2 + (size_t)b * S_ * D_;
    const float* vbase = x4 + (size_t)b * S_ * D_;
    const float* biasbase = x3 + (((size_t)b * H_ + h) * S_ + (size_t)mt * TM) * S_;

    const int r0 = warp * 16 + r;        // this thread's first row
    const int r1 = r0 + 8;
    const int pp0 = (q & 1) * 4 + (q >> 1);   // perm(2q)
    const int pp1 = pp0 + 2;                  // perm(2q+1)

    for (int t0 = 0; t0 < S_; t0 += TN) {
        __syncthreads();   // protect sK/sV from previous iteration's readers

        // ---- stage K (permuted) and V (plain) tiles ----
        #pragma unroll
        for (int i = tid; i < TN * (D_ / 4); i += NTHREADS) {
            int row = i >> 4;
            int c4  = i & 15;
            float4 kv = *reinterpret_cast<const float4*>(kbase + (size_t)(t0 + row) * D_ + c4 * 4);
            store_permuted(sK, row, c4, kv, 1.0f);
            float4 vv = *reinterpret_cast<const float4*>(vbase + (size_t)(t0 + row) * D_ + c4 * 4);
            uint4 o;
            o.x = f2tf(vv.x); o.y = f2tf(vv.y); o.z = f2tf(vv.z); o.w = f2tf(vv.w);
            *reinterpret_cast<uint4*>(sV + row * PITCH + c4 * 4) = o;
        }
        __syncthreads();

        // ---- S = Q @ K^T  (per warp: 16 rows x 64 cols) ----
        float c[8][4];
        #pragma unroll
        for (int n = 0; n < 8; ++n)
            #pragma unroll
            for (int j = 0; j < 4; ++j) c[n][j] = 0.0f;

        #pragma unroll
        for (int k = 0; k < 8; ++k) {
            uint2 qa = *reinterpret_cast<const uint2*>(sQ + r0 * PITCH + 8 * k + 2 * q);
            uint2 qb = *reinterpret_cast<const uint2*>(sQ + r1 * PITCH + 8 * k + 2 * q);
            #pragma unroll
            for (int n = 0; n < 8; ++n) {
                uint2 kb = *reinterpret_cast<const uint2*>(sK + (8 * n + r) * PITCH + 8 * k + 2 * q);
                mma_tf32(c[n], qa.x, qb.x, qa.y, qb.y, kb.x, kb.y);
            }
        }

        // ---- logits + bias -> exp -> P (smem, permuted tf32), row sums ----
        const float* brow0 = biasbase + (size_t)r0 * S_ + t0;
        const float* brow1 = biasbase + (size_t)r1 * S_ + t0;
        #pragma unroll
        for (int n = 0; n < 8; ++n) {
            float2 bb0 = *reinterpret_cast<const float2*>(brow0 + 8 * n + 2 * q);
            float2 bb1 = *reinterpret_cast<const float2*>(brow1 + 8 * n + 2 * q);
            float p0 = __expf(c[n][0] + bb0.x);
            float p1 = __expf(c[n][1] + bb0.y);
            float p2 = __expf(c[n][2] + bb1.x);
            float p3 = __expf(c[n][3] + bb1.y);
            lsum0 += p0 + p1;
            lsum1 += p2 + p3;
            sP[r0 * PITCH + 8 * n + pp0] = f2tf(p0);
            sP[r0 * PITCH + 8 * n + pp1] = f2tf(p1);
            sP[r1 * PITCH + 8 * n + pp0] = f2tf(p2);
            sP[r1 * PITCH + 8 * n + pp1] = f2tf(p3);
        }
        __syncwarp();   // each warp reads only its own 16 rows of sP

        // ---- O += P @ V ----
        #pragma unroll
        for (int k = 0; k < 8; ++k) {
            uint2 pa = *reinterpret_cast<const uint2*>(sP + r0 * PITCH + 8 * k + 2 * q);
            uint2 pb = *reinterpret_cast<const uint2*>(sP + r1 * PITCH + 8 * k + 2 * q);
            #pragma unroll
            for (int n = 0; n < 8; ++n) {
                uint32_t b0 = sV[(8 * k + q) * PITCH + 8 * n + r];
                uint32_t b1 = sV[(8 * k + q + 4) * PITCH + 8 * n + r];
                mma_tf32(accO[n], pa.x, pb.x, pa.y, pb.y, b0, b1);
            }
        }
    }

    // ---- finalize: reduce row sums across the quad, divide, store ----
    lsum0 += __shfl_xor_sync(0xffffffffu, lsum0, 1);
    lsum0 += __shfl_xor_sync(0xffffffffu, lsum0, 2);
    lsum1 += __shfl_xor_sync(0xffffffffu, lsum1, 1);
    lsum1 += __shfl_xor_sync(0xffffffffu, lsum1, 2);
    float inv0 = 1.0f / lsum0;
    float inv1 = 1.0f / lsum1;

    float* obase = out + (((size_t)b * H_ + h) * S_ + (size_t)mt * TM) * D_;
    #pragma unroll
    for (int n = 0; n < 8; ++n) {
        float2 v0 = make_float2(accO[n][0] * inv0, accO[n][1] * inv0);
        float2 v1 = make_float2(accO[n][2] * inv1, accO[n][3] * inv1);
        *reinterpret_cast<float2*>(obase + (size_t)r0 * D_ + 8 * n + 2 * q) = v0;
        *reinterpret_cast<float2*>(obase + (size_t)r1 * D_ + 8 * n + 2 * q) = v1;
    }
}

extern "C" void kernel_launch(void* const* d_in, const int* in_sizes, int n_in,
                              void* d_out, int out_size) {
    (void)in_sizes; (void)n_in; (void)out_size;
    const float* x1 = (const float*)d_in[0];
    const float* x2 = (const float*)d_in[1];
    const float* x3 = (const float*)d_in[2];
    const float* x4 = (const float*)d_in[3];
    float* out = (float*)d_out;

    cudaFuncSetAttribute(attn_bias_kernel,
                         cudaFuncAttributeMaxDynamicSharedMemorySize, SMEM_BYTES);

    dim3 grid(S_ / TM, H_, B_);   // 32 x 8 x 2 = 512 CTAs
    attn_bias_kernel<<<grid, NTHREADS, SMEM_BYTES>>>(x1, x2, x3, x4, out);
}

// round 3
// speedup vs baseline: 1.6436x; 1.6436x over previous
#include <cuda_runtime.h>
#include <cstdint>
#include <cstddef>

#define B_ 2
#define S_ 2048
#define D_ 64
#define H_ 8

#define TM 128   // rows per CTA
#define TN 64    // t-columns per main-loop iteration
#define NTHREADS 128

// pitch in 32-bit words; 72 ≡ 8 (mod 32): conflict-free LDS.64 fragment loads,
// conflict-free STS.128 staging, conflict-free bias LDS.64.
#define PITCH 72

#define SMEM_WORDS ((TM + TN + TN + TM) * PITCH)   // sQ, sK, sV, sPB
#define SMEM_BYTES (SMEM_WORDS * 4)                // 110,592 B -> 2 CTAs/SM

__device__ __forceinline__ uint32_t f2tf(float x) {
    uint32_t r;
    asm("cvt.rna.tf32.f32 %0, %1;" : "=r"(r) : "f"(x));
    return r;
}

__device__ __forceinline__ void mma_tf32(float c[4],
                                         uint32_t a0, uint32_t a1, uint32_t a2, uint32_t a3,
                                         uint32_t b0, uint32_t b1) {
    asm volatile(
        "mma.sync.aligned.m16n8k8.row.col.f32.tf32.tf32.f32 "
        "{%0,%1,%2,%3}, {%4,%5,%6,%7}, {%8,%9}, {%0,%1,%2,%3};\n"
        : "+f"(c[0]), "+f"(c[1]), "+f"(c[2]), "+f"(c[3])
        : "r"(a0), "r"(a1), "r"(a2), "r"(a3), "r"(b0), "r"(b1));
}

__device__ __forceinline__ void cp_async16(uint32_t dst_smem, const void* src) {
    asm volatile("cp.async.cg.shared.global [%0], [%1], 16;\n"
                 :: "r"(dst_smem), "l"(src));
}

// Pair-permuted staging: within each 8-col block, logical col w -> physical
// word perm(w) = (w&3)*2 + (w>>2), so mma fragment pairs (w, w+4) are adjacent
// -> LDS.64 operand loads. Thread pair (lane ^ 1) covers one 8-col block via
// shuffles; each thread emits one STS.128.
__device__ __forceinline__ void store_permuted(uint32_t* base, int row, int c4,
                                               float4 v, float scale) {
    float s0 = __shfl_xor_sync(0xffffffffu, v.x, 1);
    float s1 = __shfl_xor_sync(0xffffffffu, v.y, 1);
    float s2 = __shfl_xor_sync(0xffffffffu, v.z, 1);
    float s3 = __shfl_xor_sync(0xffffffffu, v.w, 1);
    int blk  = c4 >> 1;
    int half = c4 & 1;
    uint4 o;
    if (half == 0) {
        o.x = f2tf(v.x * scale); o.y = f2tf(s0 * scale);
        o.z = f2tf(v.y * scale); o.w = f2tf(s1 * scale);
    } else {
        o.x = f2tf(s2 * scale);  o.y = f2tf(v.z * scale);
        o.z = f2tf(s3 * scale);  o.w = f2tf(v.w * scale);
    }
    *reinterpret_cast<uint4*>(base + row * PITCH + blk * 8 + half * 4) = o;
}

__global__ void __launch_bounds__(NTHREADS, 2)
attn_bias_kernel(const float* __restrict__ x1,
                 const float* __restrict__ x2,
                 const float* __restrict__ x3,
                 const float* __restrict__ x4,
                 float* __restrict__ out) {
    const int mt = blockIdx.x;   // 0..15
    const int h  = blockIdx.y;   // 0..7
    const int b  = blockIdx.z;   // 0..1

    const int tid  = threadIdx.x;
    const int warp = tid >> 5;
    const int lane = tid & 31;
    const int r = lane >> 2;
    const int q = lane & 3;

    extern __shared__ uint32_t smem[];
    uint32_t* sQ  = smem;                 // [TM][PITCH] permuted tf32 (pre-scaled)
    uint32_t* sK  = sQ + TM * PITCH;      // [TN][PITCH] permuted tf32
    uint32_t* sV  = sK + TN * PITCH;      // [TN][PITCH] plain    tf32
    uint32_t* sPB = sV + TN * PITCH;      // [TM][PITCH] bias (linear fp32) then P (permuted tf32)
    const float* sPBf = reinterpret_cast<const float*>(sPB);
    uint32_t sPB_addr = (uint32_t)__cvta_generic_to_shared(sPB);

    // ---- stage Q tile once (pre-scaled by 1/sqrt(D) = 0.125) ----
    const float* qbase = x1 + ((size_t)b * S_ + (size_t)mt * TM) * D_;
    #pragma unroll
    for (int j = 0; j < 16; ++j) {
        int i = j * NTHREADS + tid;
        int row = i >> 4;
        int c4  = i & 15;
        float4 v = *reinterpret_cast<const float4*>(qbase + row * D_ + c4 * 4);
        store_permuted(sQ, row, c4, v, 0.125f);
    }

    float accO[2][8][4];
    #pragma unroll
    for (int mf = 0; mf < 2; ++mf)
        #pragma unroll
        for (int n = 0; n < 8; ++n)
            #pragma unroll
            for (int j = 0; j < 4; ++j) accO[mf][n][j] = 0.0f;
    float lsum[2][2] = {{0.0f, 0.0f}, {0.0f, 0.0f}};

    const float* kbase = x2 + (size_t)b * S_ * D_;
    const float* vbase = x4 + (size_t)b * S_ * D_;
    const float* biasbase = x3 + (((size_t)b * H_ + h) * S_ + (size_t)mt * TM) * S_;

    const int R0 = warp * 32;
    const int R1 = warp * 32 + 16;
    const int pp0 = (q & 1) * 4 + (q >> 1);   // perm(2q)
    const int pp1 = pp0 + 2;                  // perm(2q+1)

    for (int t0 = 0; t0 < S_; t0 += TN) {
        __syncthreads();   // prev iteration's sK/sV/sPB readers done

        // ---- issue bias tile cp.async (TM x TN floats, linear, pitch 72) ----
        const float* btile = biasbase + t0;
        #pragma unroll
        for (int j = 0; j < 16; ++j) {
            int i = j * NTHREADS + tid;
            int row = i >> 4;
            int c4  = i & 15;
            cp_async16(sPB_addr + (uint32_t)(row * PITCH + c4 * 4) * 4,
                       btile + (size_t)row * S_ + c4 * 4);
        }
        asm volatile("cp.async.commit_group;\n" ::: "memory");

        // ---- stage K (permuted) and V (plain) tiles ----
        #pragma unroll
        for (int j = 0; j < 8; ++j) {
            int i = j * NTHREADS + tid;
            int row = i >> 4;
            int c4  = i & 15;
            float4 kv = *reinterpret_cast<const float4*>(kbase + (size_t)(t0 + row) * D_ + c4 * 4);
            store_permuted(sK, row, c4, kv, 1.0f);
            float4 vv = *reinterpret_cast<const float4*>(vbase + (size_t)(t0 + row) * D_ + c4 * 4);
            uint4 o;
            o.x = f2tf(vv.x); o.y = f2tf(vv.y); o.z = f2tf(vv.z); o.w = f2tf(vv.w);
            *reinterpret_cast<uint4*>(sV + row * PITCH + c4 * 4) = o;
        }
        __syncthreads();   // sK/sV ready (bias may still be in flight)

        // ---- S = Q @ K^T  (per warp: 32 rows x 64 cols), bias lands under MMA ----
        float c[2][8][4];
        #pragma unroll
        for (int mf = 0; mf < 2; ++mf)
            #pragma unroll
            for (int n = 0; n < 8; ++n)
                #pragma unroll
                for (int j = 0; j < 4; ++j) c[mf][n][j] = 0.0f;

        #pragma unroll
        for (int k = 0; k < 8; ++k) {
            uint2 qa0 = *reinterpret_cast<const uint2*>(sQ + (R0 + r)     * PITCH + 8 * k + 2 * q);
            uint2 qb0 = *reinterpret_cast<const uint2*>(sQ + (R0 + r + 8) * PITCH + 8 * k + 2 * q);
            uint2 qa1 = *reinterpret_cast<const uint2*>(sQ + (R1 + r)     * PITCH + 8 * k + 2 * q);
            uint2 qb1 = *reinterpret_cast<const uint2*>(sQ + (R1 + r + 8) * PITCH + 8 * k + 2 * q);
            #pragma unroll
            for (int n = 0; n < 8; ++n) {
                uint2 kb = *reinterpret_cast<const uint2*>(sK + (8 * n + r) * PITCH + 8 * k + 2 * q);
                mma_tf32(c[0][n], qa0.x, qb0.x, qa0.y, qb0.y, kb.x, kb.y);
                mma_tf32(c[1][n], qa1.x, qb1.x, qa1.y, qb1.y, kb.x, kb.y);
            }
        }

        // ---- bias is needed now; wait + CTA barrier (copiers != readers) ----
        asm volatile("cp.async.wait_group 0;\n" ::: "memory");
        __syncthreads();

        // ---- logits + bias -> exp -> P (overwrite sPB, permuted tf32) ----
        #pragma unroll
        for (int mf = 0; mf < 2; ++mf) {
            const int R = (mf == 0) ? R0 : R1;
            float2 bb0[8], bb1[8];
            #pragma unroll
            for (int n = 0; n < 8; ++n) {
                bb0[n] = *reinterpret_cast<const float2*>(sPBf + (size_t)(R + r) * PITCH + 8 * n + 2 * q);
                bb1[n] = *reinterpret_cast<const float2*>(sPBf + (size_t)(R + r + 8) * PITCH + 8 * n + 2 * q);
            }
            __syncwarp();   // all bias reads for these 16 rows done before any P write
            #pragma unroll
            for (int n = 0; n < 8; ++n) {
                float p0 = __expf(c[mf][n][0] + bb0[n].x);
                float p1 = __expf(c[mf][n][1] + bb0[n].y);
                float p2 = __expf(c[mf][n][2] + bb1[n].x);
                float p3 = __expf(c[mf][n][3] + bb1[n].y);
                lsum[mf][0] += p0 + p1;
                lsum[mf][1] += p2 + p3;
                sPB[(R + r) * PITCH + 8 * n + pp0]     = f2tf(p0);
                sPB[(R + r) * PITCH + 8 * n + pp1]     = f2tf(p1);
                sPB[(R + r + 8) * PITCH + 8 * n + pp0] = f2tf(p2);
                sPB[(R + r + 8) * PITCH + 8 * n + pp1] = f2tf(p3);
            }
        }
        __syncwarp();   // each warp reads only its own 32 rows of P

        // ---- O += P @ V ----
        #pragma unroll
        for (int k = 0; k < 8; ++k) {
            uint2 pa0 = *reinterpret_cast<const uint2*>(sPB + (R0 + r)     * PITCH + 8 * k + 2 * q);
            uint2 pb0 = *reinterpret_cast<const uint2*>(sPB + (R0 + r + 8) * PITCH + 8 * k + 2 * q);
            uint2 pa1 = *reinterpret_cast<const uint2*>(sPB + (R1 + r)     * PITCH + 8 * k + 2 * q);
            uint2 pb1 = *reinterpret_cast<const uint2*>(sPB + (R1 + r + 8) * PITCH + 8 * k + 2 * q);
            #pragma unroll
            for (int n = 0; n < 8; ++n) {
                uint32_t b0 = sV[(8 * k + q)     * PITCH + 8 * n + r];
                uint32_t b1 = sV[(8 * k + q + 4) * PITCH + 8 * n + r];
                mma_tf32(accO[0][n], pa0.x, pb0.x, pa0.y, pb0.y, b0, b1);
                mma_tf32(accO[1][n], pa1.x, pb1.x, pa1.y, pb1.y, b0, b1);
            }
        }
    }

    // ---- finalize ----
    #pragma unroll
    for (int mf = 0; mf < 2; ++mf)
        #pragma unroll
        for (int j = 0; j < 2; ++j) {
            lsum[mf][j] += __shfl_xor_sync(0xffffffffu, lsum[mf][j], 1);
            lsum[mf][j] += __shfl_xor_sync(0xffffffffu, lsum[mf][j], 2);
        }

    float inv[2][2];
    inv[0][0] = 1.0f / lsum[0][0]; inv[0][1] = 1.0f / lsum[0][1];
    inv[1][0] = 1.0f / lsum[1][0]; inv[1][1] = 1.0f / lsum[1][1];

    float* obase = out + (((size_t)b * H_ + h) * S_ + (size_t)mt * TM) * D_;
    #pragma unroll
    for (int mf = 0; mf < 2; ++mf) {
        const int R = (mf == 0) ? R0 : R1;
        #pragma unroll
        for (int n = 0; n < 8; ++n) {
            float2 v0 = make_float2(accO[mf][n][0] * inv[mf][0], accO[mf][n][1] * inv[mf][0]);
            float2 v1 = make_float2(accO[mf][n][2] * inv[mf][1], accO[mf][n][3] * inv[mf][1]);
            *reinterpret_cast<float2*>(obase + (size_t)(R + r) * D_ + 8 * n + 2 * q) = v0;
            *reinterpret_cast<float2*>(obase + (size_t)(R + r + 8) * D_ + 8 * n + 2 * q) = v1;
        }
    }
}

extern "C" void kernel_launch(void* const* d_in, const int* in_sizes, int n_in,
                              void* d_out, int out_size) {
    (void)in_sizes; (void)n_in; (void)out_size;
    const float* x1 = (const float*)d_in[0];
    const float* x2 = (const float*)d_in[1];
    const float* x3 = (const float*)d_in[2];
    const float* x4 = (const float*)d_in[3];
    float* out = (float*)d_out;

    cudaFuncSetAttribute(attn_bias_kernel,
                         cudaFuncAttributeMaxDynamicSharedMemorySize, SMEM_BYTES);

    dim3 grid(S_ / TM, H_, B_);   // 16 x 8 x 2 = 256 CTAs
    attn_bias_kernel<<<grid, NTHREADS, SMEM_BYTES>>>(x1, x2, x3, x4, out);
}